// round 6
// baseline (speedup 1.0000x reference)
#include <cuda_runtime.h>
#include <cuda_bf16.h>
#include <math.h>
#include <stdint.h>

#define TSTEPS 80
#define BATCH  64
#define FDIM   4096
#define EDIM   512
#define HDIM   512
#define VDIM   13000
#define VPAD   13056
#define GDIM   2048
#define NSTEPS 160
#define MROWS  5120
#define START_ID 1

// ---------------- scratch ----------------
__device__ __align__(16) __nv_bfloat16 g_feats2[(size_t)MROWS * 2 * FDIM];   // [hi|lo]
__device__ __align__(16) __nv_bfloat16 g_Wf2   [(size_t)EDIM  * 2 * FDIM];
__device__ __align__(16) __nv_bfloat16 g_emb2  [(size_t)MROWS * 2 * EDIM];   // t-major rows
__device__ __align__(16) __nv_bfloat16 g_Wih2e [(size_t)GDIM  * 2 * EDIM];
__device__ __align__(16) __nv_bfloat16 g_Wih2d [(size_t)GDIM  * 2 * EDIM];
__device__ __align__(16) __nv_bfloat16 g_dece2 [(size_t)MROWS * 2 * EDIM];   // t-major rows
__device__ __align__(16) float         g_xgate [(size_t)NSTEPS * BATCH * GDIM]; // [s*64+b][2048]
__device__ __align__(16) __nv_bfloat16 g_hh2   [(size_t)MROWS * 2 * HDIM];   // t-major rows
__device__ __align__(16) __nv_bfloat16 g_Wo2   [(size_t)VPAD  * 2 * HDIM];
__device__ __align__(16) float         g_hbuf  [2][BATCH * HDIM];
__device__ unsigned g_bar_cnt, g_bar_gen;

// ---------------- generic-PTX helpers ----------------
__device__ __forceinline__ uint32_t s2u(const void* p) {
    uint32_t a;
    asm("{ .reg .u64 t; cvta.to.shared.u64 t, %1; cvt.u32.u64 %0, t; }" : "=r"(a) : "l"(p));
    return a;
}
__device__ __forceinline__ void cpasync16(uint32_t dst, const void* src) {
    asm volatile("cp.async.cg.shared.global [%0], [%1], 16;" :: "r"(dst), "l"(src));
}
__device__ __forceinline__ void ldm4(uint32_t* d, uint32_t addr) {
    asm volatile("ldmatrix.sync.aligned.m8n8.x4.shared.b16 {%0,%1,%2,%3}, [%4];"
        : "=r"(d[0]), "=r"(d[1]), "=r"(d[2]), "=r"(d[3]) : "r"(addr));
}
__device__ __forceinline__ void mma16816(float* c, const uint32_t* a, const uint32_t* b) {
    asm volatile("mma.sync.aligned.m16n8k16.row.col.f32.bf16.bf16.f32 "
        "{%0,%1,%2,%3}, {%4,%5,%6,%7}, {%8,%9}, {%0,%1,%2,%3};"
        : "+f"(c[0]), "+f"(c[1]), "+f"(c[2]), "+f"(c[3])
        : "r"(a[0]), "r"(a[1]), "r"(a[2]), "r"(a[3]), "r"(b[0]), "r"(b[1]));
}
__device__ __forceinline__ void fma2(unsigned long long& acc,
                                     unsigned long long a, unsigned long long b) {
    asm("fma.rn.f32x2 %0, %1, %2, %0;" : "+l"(acc) : "l"(a), "l"(b));
}

// hi/lo split write: hi at dst[0..3], lo at dst[K..K+3]
__device__ __forceinline__ void split_w4(__nv_bfloat16* dst, int K, float4 v) {
    float vv[4] = {v.x, v.y, v.z, v.w};
    __nv_bfloat16 hi[4], lo[4];
#pragma unroll
    for (int j = 0; j < 4; j++) {
        hi[j] = __float2bfloat16(vv[j]);
        lo[j] = __float2bfloat16(vv[j] - __bfloat162float(hi[j]));
    }
    *(uint64_t*)(dst)     = *(const uint64_t*)hi;
    *(uint64_t*)(dst + K) = *(const uint64_t*)lo;
}

// ---------------- prep: all weight splits + decoder gather, one kernel ----------------
#define T_WF  524288LL                    // 512 x 1024 f4
#define T_WE  (T_WF + 262144LL)           // Wih enc
#define T_WD  (T_WE + 262144LL)           // Wih dec
#define T_WO  (T_WD + 1671168LL)          // 13056 x 128 f4
#define T_GA  (T_WO + 655360LL)           // gather 5120 x 128 f4

__global__ void prep_kernel(const int* __restrict__ labels, const float* __restrict__ embed,
                            const float* __restrict__ W_frame, const float* __restrict__ W_ih,
                            const float* __restrict__ W_out,
                            __nv_bfloat16* __restrict__ Wf2,
                            __nv_bfloat16* __restrict__ Wih2e, __nv_bfloat16* __restrict__ Wih2d,
                            __nv_bfloat16* __restrict__ Wo2, __nv_bfloat16* __restrict__ dece2)
{
    const long long stride = (long long)gridDim.x * blockDim.x;
    for (long long i = (long long)blockIdx.x * blockDim.x + threadIdx.x; i < T_GA; i += stride) {
        if (i < T_WF) {
            int r = (int)(i >> 10), c4 = ((int)i & 1023) << 2;
            float4 v = *(const float4*)(W_frame + (size_t)r * FDIM + c4);
            split_w4(Wf2 + (size_t)r * (2 * FDIM) + c4, FDIM, v);
        } else if (i < T_WD) {
            long long j = i - T_WF;
            int dec = (j >= 262144LL);
            if (dec) j -= 262144LL;
            int r = (int)(j >> 7), c4 = ((int)j & 127) << 2;
            float4 v = *(const float4*)(W_ih + (size_t)r * 1024 + (dec ? 512 : 0) + c4);
            split_w4((dec ? Wih2d : Wih2e) + (size_t)r * 1024 + c4, 512, v);
        } else if (i < T_WO) {
            long long j = i - T_WD;
            int r = (int)(j >> 7), c4 = ((int)j & 127) << 2;
            float4 v = make_float4(0.f, 0.f, 0.f, 0.f);
            if (r < VDIM) v = *(const float4*)(W_out + (size_t)r * HDIM + c4);
            split_w4(Wo2 + (size_t)r * 1024 + c4, 512, v);
        } else {
            long long j = i - T_WO;
            int r = (int)(j >> 7), c4 = ((int)j & 127) << 2;   // r = t*64+b
            int t = r >> 6, b = r & 63;
            int id = (t == 0) ? START_ID : labels[b * TSTEPS + (t - 1)];
            float4 v = *(const float4*)(embed + (size_t)id * EDIM + c4);
            split_w4(dece2 + (size_t)r * 1024 + c4, 512, v);
        }
    }
}

// ---------------- feats split (big, separate) ----------------
__global__ void fsplit_kernel(const float* __restrict__ feats, __nv_bfloat16* __restrict__ dst)
{
    const long long TOT = (long long)MROWS * 1024;
    const long long stride = (long long)gridDim.x * blockDim.x;
    for (long long i = (long long)blockIdx.x * blockDim.x + threadIdx.x; i < TOT; i += stride) {
        int r = (int)(i >> 10), c4 = ((int)i & 1023) << 2;
        float4 v = *(const float4*)(feats + (size_t)r * FDIM + c4);
        split_w4(dst + (size_t)r * (2 * FDIM) + c4, FDIM, v);
    }
}

// ---------------- mma.sync bf16 GEMM, 2-segment exact-split ----------------
// A rows: [Ahi(K) | Alo(K)], B rows: [Bhi | Blo]. Computes AhiBhi + AhiBlo + AloBhi.
// CTA tile 128x128 (m = blockIdx.x), K-chunk 64, double-buffered cp.async.
// outMode: 0 direct; 1 logits remap (t-major -> b*80+t); 2 embed remap (b-major -> t*64+b).
// outBf: write bf16 hi/lo dual rows (width ldc = 2*Nreal) instead of fp32.
#define BUFSZ 32768

__device__ __forceinline__ void ld_chunk(uint32_t sbase,
    const __nv_bfloat16* __restrict__ Ab, const __nv_bfloat16* __restrict__ Bb,
    int lda, int ao, int bo, int tid)
{
    const __nv_bfloat16* ap = Ab + ao;
    const __nv_bfloat16* bp = Bb + bo;
#pragma unroll
    for (int u = 0; u < 4; u++) {
        int idx = u * 256 + tid, r = idx >> 3, q = idx & 7;
        cpasync16(sbase + r * 128 + ((q ^ (r & 7)) << 4), ap + (size_t)r * lda + q * 8);
    }
#pragma unroll
    for (int u = 0; u < 4; u++) {
        int idx = u * 256 + tid, r = idx >> 3, q = idx & 7;
        cpasync16(sbase + 16384 + r * 128 + ((q ^ (r & 7)) << 4), bp + (size_t)r * lda + q * 8);
    }
}

__global__ __launch_bounds__(256) void mma_tc(
    const __nv_bfloat16* __restrict__ A, const __nv_bfloat16* __restrict__ B,
    const float* __restrict__ bias1, const float* __restrict__ bias2,
    void* __restrict__ Cv, int K, int Nreal, int ldc, int outMode, int outBf)
{
    extern __shared__ char smc[];
    const uint32_t sbase = s2u(smc);
    const int tid = threadIdx.x, lane = tid & 31, wid = tid >> 5;
    const int wm = wid & 3, wn = wid >> 2;
    const int m0 = blockIdx.x * 128, n0 = blockIdx.y * 128;
    const int lda = 2 * K;
    const int KC = K >> 6, NC = 3 * KC;
    const __nv_bfloat16* Ab = A + (size_t)m0 * lda;
    const __nv_bfloat16* Bb = B + (size_t)n0 * lda;

    float acc[2][8][4];
#pragma unroll
    for (int a = 0; a < 2; a++)
#pragma unroll
        for (int b = 0; b < 8; b++)
#pragma unroll
            for (int d = 0; d < 4; d++) acc[a][b][d] = 0.f;

    ld_chunk(sbase, Ab, Bb, lda, 0, 0, tid);
    asm volatile("cp.async.commit_group;" ::: "memory");

    int segN = 0, kcN = 0;
    for (int c = 0; c < NC; c++) {
        if (c + 1 < NC) {
            if (++kcN == KC) { kcN = 0; segN++; }
            int ao = ((segN == 2) ? K : 0) + (kcN << 6);
            int bo = ((segN == 1) ? K : 0) + (kcN << 6);
            ld_chunk(sbase + ((c + 1) & 1) * BUFSZ, Ab, Bb, lda, ao, bo, tid);
            asm volatile("cp.async.commit_group;" ::: "memory");
            asm volatile("cp.async.wait_group 1;" ::: "memory");
        } else {
            asm volatile("cp.async.wait_group 0;" ::: "memory");
        }
        __syncthreads();

        const uint32_t sa = sbase + (c & 1) * BUFSZ;
        const uint32_t sb = sa + 16384;
#pragma unroll
        for (int ks = 0; ks < 4; ks++) {
            uint32_t af[2][4];
#pragma unroll
            for (int mt = 0; mt < 2; mt++) {
                int r = wm * 32 + mt * 16 + (lane & 15);
                int q = 2 * ks + (lane >> 4);
                ldm4(af[mt], sa + r * 128 + ((q ^ (r & 7)) << 4));
            }
            uint32_t bf[4][4];
#pragma unroll
            for (int bp2 = 0; bp2 < 4; bp2++) {
                int r = wn * 64 + (bp2 * 2 + (lane >> 4)) * 8 + (lane & 7);
                int q = 2 * ks + ((lane >> 3) & 1);
                ldm4(bf[bp2], sb + r * 128 + ((q ^ (r & 7)) << 4));
            }
#pragma unroll
            for (int mt = 0; mt < 2; mt++)
#pragma unroll
                for (int nt = 0; nt < 8; nt++)
                    mma16816(acc[mt][nt], af[mt], &bf[nt >> 1][(nt & 1) * 2]);
        }
        __syncthreads();   // all warps done reading buf[c&1] before it is overwritten
    }

    const int mb = m0 + wm * 32, nb = n0 + wn * 64;
#pragma unroll
    for (int mt = 0; mt < 2; mt++)
#pragma unroll
        for (int half = 0; half < 2; half++) {
            int r = mb + mt * 16 + (lane >> 2) + half * 8;
            int rr;
            if (outMode == 1)      rr = (r & 63) * 80 + (r >> 6);
            else if (outMode == 2) rr = (r % 80) * 64 + (r / 80);
            else                   rr = r;
#pragma unroll
            for (int nt = 0; nt < 8; nt++) {
                int cb = nb + nt * 8 + (lane & 3) * 2;
                if (cb < Nreal) {
                    float2 bv = *(const float2*)(bias1 + cb);
                    if (bias2) {
                        float2 b2 = *(const float2*)(bias2 + cb);
                        bv.x += b2.x; bv.y += b2.y;
                    }
                    float vx = acc[mt][nt][half * 2 + 0] + bv.x;
                    float vy = acc[mt][nt][half * 2 + 1] + bv.y;
                    if (outBf) {
                        __nv_bfloat16* op = (__nv_bfloat16*)Cv + (size_t)rr * ldc;
                        __nv_bfloat16 h0 = __float2bfloat16(vx), h1 = __float2bfloat16(vy);
                        __nv_bfloat16 l0 = __float2bfloat16(vx - __bfloat162float(h0));
                        __nv_bfloat16 l1 = __float2bfloat16(vy - __bfloat162float(h1));
                        *(__nv_bfloat162*)(op + cb)         = __halves2bfloat162(h0, h1);
                        *(__nv_bfloat162*)(op + Nreal + cb) = __halves2bfloat162(l0, l1);
                    } else {
                        float* op = (float*)Cv + (size_t)rr * ldc;
                        *(float2*)(op + cb) = make_float2(vx, vy);
                    }
                }
            }
        }
}

// ---------------- persistent LSTM ----------------
#define RCTAS 128
#define HPAD  516

__device__ __forceinline__ void grid_sync()
{
    __syncthreads();
    if (threadIdx.x == 0) {
        unsigned* cp = &g_bar_cnt;
        unsigned* gp = &g_bar_gen;
        unsigned gen;
        asm volatile("ld.relaxed.gpu.global.u32 %0, [%1];" : "=r"(gen) : "l"(gp) : "memory");
        unsigned old;
        asm volatile("atom.release.gpu.global.add.u32 %0, [%1], 1;"
                     : "=r"(old) : "l"(cp) : "memory");
        if (old == RCTAS - 1) {
            asm volatile("st.relaxed.gpu.global.u32 [%0], %1;" :: "l"(cp), "r"(0u) : "memory");
            asm volatile("st.release.gpu.global.u32 [%0], %1;" :: "l"(gp), "r"(gen + 1u) : "memory");
        } else {
            unsigned g;
            do {
                asm volatile("ld.acquire.gpu.global.u32 %0, [%1];" : "=r"(g) : "l"(gp) : "memory");
            } while (g == gen);
        }
    }
    __syncthreads();
}

__device__ __forceinline__ float sigf(float x) {
    return __fdividef(1.f, 1.f + __expf(-x));
}
__device__ __forceinline__ float tanhfast(float x) {
    float e = __expf(-2.f * fabsf(x));
    float t = __fdividef(1.f - e, 1.f + e);
    return copysignf(t, x);
}

__global__ __launch_bounds__(256, 1) void lstm_kernel(
    const float* __restrict__ Whh, const float* __restrict__ xg,
    __nv_bfloat16* __restrict__ hh2)
{
    extern __shared__ float sm[];
    float* ws = sm;                      // [8 hu][4 gate][512 k]
    float* hs = sm + 16384;              // [32 b][HPAD]
    float* xs = hs + 32 * HPAD;          // 2 x [4 g][32 b][9]

    const int tid = threadIdx.x;
    const int b_l = tid & 31, hu_l = tid >> 5;
    const int ct_b = blockIdx.x & 1, ct_h = blockIdx.x >> 1;
    const int hu = ct_h * 8 + hu_l, b = ct_b * 32 + b_l;

    for (int i = tid; i < 16384; i += 256) {
        int h = i >> 11, g = (i >> 9) & 3, k = i & 511;
        ws[i] = Whh[(size_t)(g * 512 + ct_h * 8 + h) * 512 + k];
    }
    g_hbuf[0][blockIdx.x * 256 + tid] = 0.f;

    const int sg = tid >> 6, sb2 = (tid >> 1) & 31, shalf = tid & 1;
    const size_t xoff = (size_t)(ct_b * 32 + sb2) * GDIM + sg * 512 + ct_h * 8 + shalf * 4;
    // preload x(0)
    {
        float4 xv = *(const float4*)(xg + xoff);
        float* d = xs + sg * 288 + sb2 * 9 + shalf * 4;
        d[0] = xv.x; d[1] = xv.y; d[2] = xv.z; d[3] = xv.w;
    }
    float cc = 0.f;
    grid_sync();

    int cur = 0;
    for (int s = 0; s < NSTEPS; s++) {
        // h stage (critical path)
        const float4* src = (const float4*)(g_hbuf[cur] + (size_t)ct_b * 32 * 512);
#pragma unroll
        for (int j = 0; j < 16; j++) {
            int idx = tid + j * 256;
            float4 v = __ldcg(src + idx);
            int bb = idx >> 7, kq = (idx & 127) << 2;
            *(float4*)(hs + bb * HPAD + kq) = v;
        }
        // prefetch x(s+1) into the other xs buffer (consumed after next step's sync)
        if (s + 1 < NSTEPS) {
            float4 xv = *(const float4*)(xg + (size_t)(s + 1) * (BATCH * GDIM) + xoff);
            float* d = xs + ((s + 1) & 1) * 1152 + sg * 288 + sb2 * 9 + shalf * 4;
            d[0] = xv.x; d[1] = xv.y; d[2] = xv.z; d[3] = xv.w;
        }
        __syncthreads();

        const float* xcur = xs + (s & 1) * 1152;
        float x0 = xcur[0 * 288 + b_l * 9 + hu_l];
        float x1 = xcur[1 * 288 + b_l * 9 + hu_l];
        float x2 = xcur[2 * 288 + b_l * 9 + hu_l];
        float x3 = xcur[3 * 288 + b_l * 9 + hu_l];

        unsigned long long a0 = 0ull, a1 = 0ull, a2 = 0ull, a3 = 0ull;
        const longlong2* hp = (const longlong2*)(hs + b_l * HPAD);
        const longlong2* w0 = (const longlong2*)(ws + (hu_l * 4 + 0) * 512);
        const longlong2* w1 = (const longlong2*)(ws + (hu_l * 4 + 1) * 512);
        const longlong2* w2 = (const longlong2*)(ws + (hu_l * 4 + 2) * 512);
        const longlong2* w3 = (const longlong2*)(ws + (hu_l * 4 + 3) * 512);
#pragma unroll 2
        for (int k4 = 0; k4 < 128; k4++) {
            longlong2 h2 = hp[k4];
            longlong2 w;
            w = w0[k4];
            fma2(a0, (unsigned long long)h2.x, (unsigned long long)w.x);
            fma2(a0, (unsigned long long)h2.y, (unsigned long long)w.y);
            w = w1[k4];
            fma2(a1, (unsigned long long)h2.x, (unsigned long long)w.x);
            fma2(a1, (unsigned long long)h2.y, (unsigned long long)w.y);
            w = w2[k4];
            fma2(a2, (unsigned long long)h2.x, (unsigned long long)w.x);
            fma2(a2, (unsigned long long)h2.y, (unsigned long long)w.y);
            w = w3[k4];
            fma2(a3, (unsigned long long)h2.x, (unsigned long long)w.x);
            fma2(a3, (unsigned long long)h2.y, (unsigned long long)w.y);
        }
        float lo, hi, gi, gf, gg, go;
        asm("mov.b64 {%0,%1}, %2;" : "=f"(lo), "=f"(hi) : "l"(a0)); gi = lo + hi + x0;
        asm("mov.b64 {%0,%1}, %2;" : "=f"(lo), "=f"(hi) : "l"(a1)); gf = lo + hi + x1;
        asm("mov.b64 {%0,%1}, %2;" : "=f"(lo), "=f"(hi) : "l"(a2)); gg = lo + hi + x2;
        asm("mov.b64 {%0,%1}, %2;" : "=f"(lo), "=f"(hi) : "l"(a3)); go = lo + hi + x3;

        float iv = sigf(gi), fv = sigf(gf), gv = tanhfast(gg), ov = sigf(go);
        cc = fv * cc + iv * gv;
        float hv = ov * tanhfast(cc);

        g_hbuf[cur ^ 1][(size_t)b * 512 + hu] = hv;
        if (s >= TSTEPS) {
            int t = s - TSTEPS;
            __nv_bfloat16 hb = __float2bfloat16(hv);
            __nv_bfloat16 lb = __float2bfloat16(hv - __bfloat162float(hb));
            hh2[(size_t)(t * 64 + b) * 1024 + hu]       = hb;
            hh2[(size_t)(t * 64 + b) * 1024 + 512 + hu] = lb;
        }

        grid_sync();
        cur ^= 1;
    }
}

// ---------------- launch ----------------
extern "C" void kernel_launch(void* const* d_in, const int* in_sizes, int n_in,
                              void* d_out, int out_size)
{
    const float* feats   = (const float*)d_in[0];
    const int*   labels  = (const int*)  d_in[1];
    const float* W_frame = (const float*)d_in[2];
    const float* b_frame = (const float*)d_in[3];
    const float* embed   = (const float*)d_in[4];
    const float* W_ih    = (const float*)d_in[5];
    const float* W_hh    = (const float*)d_in[6];
    const float* b_ih    = (const float*)d_in[7];
    const float* b_hh    = (const float*)d_in[8];
    const float* W_out   = (const float*)d_in[9];
    const float* b_out   = (const float*)d_in[10];
    float* out = (float*)d_out;

    float* p_xgate;
    __nv_bfloat16 *p_feats2, *p_Wf2, *p_emb2, *p_Wih2e, *p_Wih2d, *p_dece2, *p_hh2, *p_Wo2;
    cudaGetSymbolAddress((void**)&p_xgate,  g_xgate);
    cudaGetSymbolAddress((void**)&p_feats2, g_feats2);
    cudaGetSymbolAddress((void**)&p_Wf2,    g_Wf2);
    cudaGetSymbolAddress((void**)&p_emb2,   g_emb2);
    cudaGetSymbolAddress((void**)&p_Wih2e,  g_Wih2e);
    cudaGetSymbolAddress((void**)&p_Wih2d,  g_Wih2d);
    cudaGetSymbolAddress((void**)&p_dece2,  g_dece2);
    cudaGetSymbolAddress((void**)&p_hh2,    g_hh2);
    cudaGetSymbolAddress((void**)&p_Wo2,    g_Wo2);

    const int smem_lstm = (16384 + 32 * HPAD + 2 * 1152) * sizeof(float);
    cudaFuncSetAttribute(lstm_kernel, cudaFuncAttributeMaxDynamicSharedMemorySize, smem_lstm);
    const int smem_tc = 2 * BUFSZ;
    cudaFuncSetAttribute(mma_tc, cudaFuncAttributeMaxDynamicSharedMemorySize, smem_tc);

    // [0] weight splits + decoder gather (fused)
    prep_kernel<<<1184, 256>>>(labels, embed, W_frame, W_ih, W_out,
                               p_Wf2, p_Wih2e, p_Wih2d, p_Wo2, p_dece2);
    // [1] feats split
    fsplit_kernel<<<1184, 256>>>(feats, p_feats2);
    // [2] frame embedding -> g_emb2 (bf16 dual, t-major rows), K=4096
    {
        dim3 grid(MROWS / 128, EDIM / 128);
        mma_tc<<<grid, 256, smem_tc>>>(p_feats2, p_Wf2, b_frame, nullptr,
                                       p_emb2, FDIM, EDIM, 2 * EDIM, 2, 1);
    }
    // [3] encoder x-gates, K=512
    {
        dim3 grid(MROWS / 128, GDIM / 128);
        mma_tc<<<grid, 256, smem_tc>>>(p_emb2, p_Wih2e, b_ih, b_hh,
                                       p_xgate, EDIM, GDIM, GDIM, 0, 0);
    }
    // [4] decoder x-gates, K=512
    {
        dim3 grid(MROWS / 128, GDIM / 128);
        mma_tc<<<grid, 256, smem_tc>>>(p_dece2, p_Wih2d, b_ih, b_hh,
                                       p_xgate + (size_t)MROWS * GDIM, EDIM, GDIM, GDIM, 0, 0);
    }
    // [5] recurrence (profiled launch)
    lstm_kernel<<<RCTAS, 256, smem_lstm>>>(W_hh, p_xgate, p_hh2);
    // [6] logits, K=512
    {
        dim3 grid(MROWS / 128, VPAD / 128);
        mma_tc<<<grid, 256, smem_tc>>>(p_hh2, p_Wo2, b_out, nullptr,
                                       out, HDIM, VDIM, VDIM, 1, 0);
    }
}

// round 7
// speedup vs baseline: 1.0235x; 1.0235x over previous
#include <cuda_runtime.h>
#include <cuda_bf16.h>
#include <math.h>
#include <stdint.h>

#define TSTEPS 80
#define BATCH  64
#define FDIM   4096
#define EDIM   512
#define HDIM   512
#define VDIM   13000
#define VPAD   13056
#define GDIM   2048
#define NSTEPS 160
#define MROWS  5120
#define START_ID 1

// ---------------- scratch ----------------
__device__ __align__(16) __nv_bfloat16 g_feats2[(size_t)MROWS * 2 * FDIM];   // [hi|lo]
__device__ __align__(16) __nv_bfloat16 g_Wf2   [(size_t)EDIM  * 2 * FDIM];
__device__ __align__(16) __nv_bfloat16 g_emb2  [(size_t)MROWS * 2 * EDIM];   // t-major rows
__device__ __align__(16) __nv_bfloat16 g_Wih2e [(size_t)GDIM  * 2 * EDIM];
__device__ __align__(16) __nv_bfloat16 g_Wih2d [(size_t)GDIM  * 2 * EDIM];
__device__ __align__(16) __nv_bfloat16 g_dece2 [(size_t)MROWS * 2 * EDIM];   // t-major rows
__device__ __align__(16) float         g_xgate [(size_t)NSTEPS * BATCH * GDIM]; // [s*64+b][2048]
__device__ __align__(16) __nv_bfloat16 g_hh2   [(size_t)MROWS * 2 * HDIM];   // t-major rows
__device__ __align__(16) __nv_bfloat16 g_Wo2   [(size_t)VPAD  * 2 * HDIM];
__device__ __align__(16) float         g_hbuf  [2][BATCH * HDIM];
__device__ unsigned g_bar_cnt[2], g_bar_gen[2];

// ---------------- generic-PTX helpers ----------------
__device__ __forceinline__ uint32_t s2u(const void* p) {
    uint32_t a;
    asm("{ .reg .u64 t; cvta.to.shared.u64 t, %1; cvt.u32.u64 %0, t; }" : "=r"(a) : "l"(p));
    return a;
}
__device__ __forceinline__ void cpasync16(uint32_t dst, const void* src) {
    asm volatile("cp.async.cg.shared.global [%0], [%1], 16;" :: "r"(dst), "l"(src));
}
__device__ __forceinline__ void ldm4(uint32_t* d, uint32_t addr) {
    asm volatile("ldmatrix.sync.aligned.m8n8.x4.shared.b16 {%0,%1,%2,%3}, [%4];"
        : "=r"(d[0]), "=r"(d[1]), "=r"(d[2]), "=r"(d[3]) : "r"(addr));
}
__device__ __forceinline__ void mma16816(float* c, const uint32_t* a, const uint32_t* b) {
    asm volatile("mma.sync.aligned.m16n8k16.row.col.f32.bf16.bf16.f32 "
        "{%0,%1,%2,%3}, {%4,%5,%6,%7}, {%8,%9}, {%0,%1,%2,%3};"
        : "+f"(c[0]), "+f"(c[1]), "+f"(c[2]), "+f"(c[3])
        : "r"(a[0]), "r"(a[1]), "r"(a[2]), "r"(a[3]), "r"(b[0]), "r"(b[1]));
}
__device__ __forceinline__ void fma2(unsigned long long& acc,
                                     unsigned long long a, unsigned long long b) {
    asm("fma.rn.f32x2 %0, %1, %2, %0;" : "+l"(acc) : "l"(a), "l"(b));
}

// hi/lo split write: hi at dst[0..3], lo at dst[K..K+3]
__device__ __forceinline__ void split_w4(__nv_bfloat16* dst, int K, float4 v) {
    float vv[4] = {v.x, v.y, v.z, v.w};
    __nv_bfloat16 hi[4], lo[4];
#pragma unroll
    for (int j = 0; j < 4; j++) {
        hi[j] = __float2bfloat16(vv[j]);
        lo[j] = __float2bfloat16(vv[j] - __bfloat162float(hi[j]));
    }
    *(uint64_t*)(dst)     = *(const uint64_t*)hi;
    *(uint64_t*)(dst + K) = *(const uint64_t*)lo;
}

// ---------------- prep: all weight splits + decoder gather ----------------
#define T_WF  524288LL
#define T_WE  (T_WF + 262144LL)
#define T_WD  (T_WE + 262144LL)
#define T_WO  (T_WD + 1671168LL)
#define T_GA  (T_WO + 655360LL)

__global__ void prep_kernel(const int* __restrict__ labels, const float* __restrict__ embed,
                            const float* __restrict__ W_frame, const float* __restrict__ W_ih,
                            const float* __restrict__ W_out,
                            __nv_bfloat16* __restrict__ Wf2,
                            __nv_bfloat16* __restrict__ Wih2e, __nv_bfloat16* __restrict__ Wih2d,
                            __nv_bfloat16* __restrict__ Wo2, __nv_bfloat16* __restrict__ dece2)
{
    const long long stride = (long long)gridDim.x * blockDim.x;
    for (long long i = (long long)blockIdx.x * blockDim.x + threadIdx.x; i < T_GA; i += stride) {
        if (i < T_WF) {
            int r = (int)(i >> 10), c4 = ((int)i & 1023) << 2;
            float4 v = *(const float4*)(W_frame + (size_t)r * FDIM + c4);
            split_w4(Wf2 + (size_t)r * (2 * FDIM) + c4, FDIM, v);
        } else if (i < T_WD) {
            long long j = i - T_WF;
            int dec = (j >= 262144LL);
            if (dec) j -= 262144LL;
            int r = (int)(j >> 7), c4 = ((int)j & 127) << 2;
            float4 v = *(const float4*)(W_ih + (size_t)r * 1024 + (dec ? 512 : 0) + c4);
            split_w4((dec ? Wih2d : Wih2e) + (size_t)r * 1024 + c4, 512, v);
        } else if (i < T_WO) {
            long long j = i - T_WD;
            int r = (int)(j >> 7), c4 = ((int)j & 127) << 2;
            float4 v = make_float4(0.f, 0.f, 0.f, 0.f);
            if (r < VDIM) v = *(const float4*)(W_out + (size_t)r * HDIM + c4);
            split_w4(Wo2 + (size_t)r * 1024 + c4, 512, v);
        } else {
            long long j = i - T_WO;
            int r = (int)(j >> 7), c4 = ((int)j & 127) << 2;   // r = t*64+b
            int t = r >> 6, b = r & 63;
            int id = (t == 0) ? START_ID : labels[b * TSTEPS + (t - 1)];
            float4 v = *(const float4*)(embed + (size_t)id * EDIM + c4);
            split_w4(dece2 + (size_t)r * 1024 + c4, 512, v);
        }
    }
}

__global__ void fsplit_kernel(const float* __restrict__ feats, __nv_bfloat16* __restrict__ dst)
{
    const long long TOT = (long long)MROWS * 1024;
    const long long stride = (long long)gridDim.x * blockDim.x;
    for (long long i = (long long)blockIdx.x * blockDim.x + threadIdx.x; i < TOT; i += stride) {
        int r = (int)(i >> 10), c4 = ((int)i & 1023) << 2;
        float4 v = *(const float4*)(feats + (size_t)r * FDIM + c4);
        split_w4(dst + (size_t)r * (2 * FDIM) + c4, FDIM, v);
    }
}

// ---------------- mma.sync bf16 GEMM, 2-segment exact-split ----------------
// A rows: [Ahi(K) | Alo(K)], B rows: [Bhi | Blo]. Computes AhiBhi + AhiBlo + AloBhi.
#define BUFSZ 32768

__device__ __forceinline__ void ld_chunk(uint32_t sbase,
    const __nv_bfloat16* __restrict__ Ab, const __nv_bfloat16* __restrict__ Bb,
    int lda, int ao, int bo, int tid)
{
    const __nv_bfloat16* ap = Ab + ao;
    const __nv_bfloat16* bp = Bb + bo;
#pragma unroll
    for (int u = 0; u < 4; u++) {
        int idx = u * 256 + tid, r = idx >> 3, q = idx & 7;
        cpasync16(sbase + r * 128 + ((q ^ (r & 7)) << 4), ap + (size_t)r * lda + q * 8);
    }
#pragma unroll
    for (int u = 0; u < 4; u++) {
        int idx = u * 256 + tid, r = idx >> 3, q = idx & 7;
        cpasync16(sbase + 16384 + r * 128 + ((q ^ (r & 7)) << 4), bp + (size_t)r * lda + q * 8);
    }
}

__global__ __launch_bounds__(256) void mma_tc(
    const __nv_bfloat16* __restrict__ A, const __nv_bfloat16* __restrict__ B,
    const float* __restrict__ bias1, const float* __restrict__ bias2,
    void* __restrict__ Cv, int K, int Nreal, int ldc, int outMode, int outBf)
{
    extern __shared__ char smc[];
    const uint32_t sbase = s2u(smc);
    const int tid = threadIdx.x, lane = tid & 31, wid = tid >> 5;
    const int wm = wid & 3, wn = wid >> 2;
    const int m0 = blockIdx.x * 128, n0 = blockIdx.y * 128;
    const int lda = 2 * K;
    const int KC = K >> 6, NC = 3 * KC;
    const __nv_bfloat16* Ab = A + (size_t)m0 * lda;
    const __nv_bfloat16* Bb = B + (size_t)n0 * lda;

    float acc[2][8][4];
#pragma unroll
    for (int a = 0; a < 2; a++)
#pragma unroll
        for (int b = 0; b < 8; b++)
#pragma unroll
            for (int d = 0; d < 4; d++) acc[a][b][d] = 0.f;

    ld_chunk(sbase, Ab, Bb, lda, 0, 0, tid);
    asm volatile("cp.async.commit_group;" ::: "memory");

    int segN = 0, kcN = 0;
    for (int c = 0; c < NC; c++) {
        asm volatile("cp.async.wait_group 0;" ::: "memory");
        __syncthreads();   // buf[c&1] ready AND all warps done with buf[(c+1)&1]

        if (c + 1 < NC) {
            if (++kcN == KC) { kcN = 0; segN++; }
            int ao = ((segN == 2) ? K : 0) + (kcN << 6);
            int bo = ((segN == 1) ? K : 0) + (kcN << 6);
            ld_chunk(sbase + ((c + 1) & 1) * BUFSZ, Ab, Bb, lda, ao, bo, tid);
            asm volatile("cp.async.commit_group;" ::: "memory");
        }

        const uint32_t sa = sbase + (c & 1) * BUFSZ;
        const uint32_t sb = sa + 16384;
#pragma unroll
        for (int ks = 0; ks < 4; ks++) {
            uint32_t af[2][4];
#pragma unroll
            for (int mt = 0; mt < 2; mt++) {
                int r = wm * 32 + mt * 16 + (lane & 15);
                int q = 2 * ks + (lane >> 4);
                ldm4(af[mt], sa + r * 128 + ((q ^ (r & 7)) << 4));
            }
            uint32_t bf[4][4];
#pragma unroll
            for (int bp2 = 0; bp2 < 4; bp2++) {
                int r = wn * 64 + (bp2 * 2 + (lane >> 4)) * 8 + (lane & 7);
                int q = 2 * ks + ((lane >> 3) & 1);
                ldm4(bf[bp2], sb + r * 128 + ((q ^ (r & 7)) << 4));
            }
#pragma unroll
            for (int mt = 0; mt < 2; mt++)
#pragma unroll
                for (int nt = 0; nt < 8; nt++)
                    mma16816(acc[mt][nt], af[mt], &bf[nt >> 1][(nt & 1) * 2]);
        }
    }

    const int mb = m0 + wm * 32, nb = n0 + wn * 64;
#pragma unroll
    for (int mt = 0; mt < 2; mt++)
#pragma unroll
        for (int half = 0; half < 2; half++) {
            int r = mb + mt * 16 + (lane >> 2) + half * 8;
            int rr;
            if (outMode == 1)      rr = (r & 63) * 80 + (r >> 6);
            else if (outMode == 2) rr = (r % 80) * 64 + (r / 80);
            else                   rr = r;
#pragma unroll
            for (int nt = 0; nt < 8; nt++) {
                int cb = nb + nt * 8 + (lane & 3) * 2;
                if (cb < Nreal) {
                    float2 bv = *(const float2*)(bias1 + cb);
                    if (bias2) {
                        float2 b2 = *(const float2*)(bias2 + cb);
                        bv.x += b2.x; bv.y += b2.y;
                    }
                    float vx = acc[mt][nt][half * 2 + 0] + bv.x;
                    float vy = acc[mt][nt][half * 2 + 1] + bv.y;
                    if (outBf) {
                        __nv_bfloat16* op = (__nv_bfloat16*)Cv + (size_t)rr * ldc;
                        __nv_bfloat16 h0 = __float2bfloat16(vx), h1 = __float2bfloat16(vy);
                        __nv_bfloat16 l0 = __float2bfloat16(vx - __bfloat162float(h0));
                        __nv_bfloat16 l1 = __float2bfloat16(vy - __bfloat162float(h1));
                        *(__nv_bfloat162*)(op + cb)         = __halves2bfloat162(h0, h1);
                        *(__nv_bfloat162*)(op + Nreal + cb) = __halves2bfloat162(l0, l1);
                    } else {
                        float* op = (float*)Cv + (size_t)rr * ldc;
                        *(float2*)(op + cb) = make_float2(vx, vy);
                    }
                }
            }
        }
}

// ---------------- persistent LSTM ----------------
#define RCTAS 128
#define GSIZE 64      // CTAs per batch-half barrier group
#define HPAD  516

__device__ __forceinline__ void grid_sync(int grp)
{
    __syncthreads();
    if (threadIdx.x == 0) {
        unsigned* cp = &g_bar_cnt[grp];
        unsigned* gp = &g_bar_gen[grp];
        unsigned gen;
        asm volatile("ld.relaxed.gpu.global.u32 %0, [%1];" : "=r"(gen) : "l"(gp) : "memory");
        unsigned old;
        asm volatile("atom.release.gpu.global.add.u32 %0, [%1], 1;"
                     : "=r"(old) : "l"(cp) : "memory");
        if (old == GSIZE - 1) {
            asm volatile("st.relaxed.gpu.global.u32 [%0], %1;" :: "l"(cp), "r"(0u) : "memory");
            asm volatile("st.release.gpu.global.u32 [%0], %1;" :: "l"(gp), "r"(gen + 1u) : "memory");
        } else {
            unsigned g;
            do {
                asm volatile("ld.acquire.gpu.global.u32 %0, [%1];" : "=r"(g) : "l"(gp) : "memory");
            } while (g == gen);
        }
    }
    __syncthreads();
}

__device__ __forceinline__ float sigf(float x) {
    return __fdividef(1.f, 1.f + __expf(-x));
}
__device__ __forceinline__ float tanhfast(float x) {
    float e = __expf(-2.f * fabsf(x));
    float t = __fdividef(1.f - e, 1.f + e);
    return copysignf(t, x);
}

__global__ __launch_bounds__(256, 1) void lstm_kernel(
    const float* __restrict__ Whh, const float* __restrict__ xg,
    __nv_bfloat16* __restrict__ hh2)
{
    extern __shared__ float sm[];
    float* ws = sm;                      // [8 hu][4 gate][512 k]
    float* hs = sm + 16384;              // [32 b][HPAD]
    float* xs = hs + 32 * HPAD;          // 2 x [4 g][32 b][9]

    const int tid = threadIdx.x;
    const int b_l = tid & 31, hu_l = tid >> 5;
    const int ct_b = blockIdx.x & 1, ct_h = blockIdx.x >> 1;
    const int hu = ct_h * 8 + hu_l, b = ct_b * 32 + b_l;

    for (int i = tid; i < 16384; i += 256) {
        int h = i >> 11, g = (i >> 9) & 3, k = i & 511;
        ws[i] = Whh[(size_t)(g * 512 + ct_h * 8 + h) * 512 + k];
    }
    g_hbuf[0][blockIdx.x * 256 + tid] = 0.f;

    const int sg = tid >> 6, sb2 = (tid >> 1) & 31, shalf = tid & 1;
    const size_t xoff = (size_t)(ct_b * 32 + sb2) * GDIM + sg * 512 + ct_h * 8 + shalf * 4;
    {
        float4 xv = *(const float4*)(xg + xoff);
        float* d = xs + sg * 288 + sb2 * 9 + shalf * 4;
        d[0] = xv.x; d[1] = xv.y; d[2] = xv.z; d[3] = xv.w;
    }
    float cc = 0.f;
    grid_sync(ct_b);

    int cur = 0;
    for (int s = 0; s < NSTEPS; s++) {
        // h stage (critical path)
        const float4* src = (const float4*)(g_hbuf[cur] + (size_t)ct_b * 32 * 512);
#pragma unroll
        for (int j = 0; j < 16; j++) {
            int idx = tid + j * 256;
            float4 v = __ldcg(src + idx);
            int bb = idx >> 7, kq = (idx & 127) << 2;
            *(float4*)(hs + bb * HPAD + kq) = v;
        }
        if (s + 1 < NSTEPS) {
            float4 xv = *(const float4*)(xg + (size_t)(s + 1) * (BATCH * GDIM) + xoff);
            float* d = xs + ((s + 1) & 1) * 1152 + sg * 288 + sb2 * 9 + shalf * 4;
            d[0] = xv.x; d[1] = xv.y; d[2] = xv.z; d[3] = xv.w;
        }
        __syncthreads();

        const float* xcur = xs + (s & 1) * 1152;
        float x0 = xcur[0 * 288 + b_l * 9 + hu_l];
        float x1 = xcur[1 * 288 + b_l * 9 + hu_l];
        float x2 = xcur[2 * 288 + b_l * 9 + hu_l];
        float x3 = xcur[3 * 288 + b_l * 9 + hu_l];

        // 8 independent f32x2 accumulator chains (4 gates x even/odd k4)
        unsigned long long a0 = 0ull, a1 = 0ull, a2 = 0ull, a3 = 0ull;
        unsigned long long e0 = 0ull, e1 = 0ull, e2 = 0ull, e3 = 0ull;
        const longlong2* hp = (const longlong2*)(hs + b_l * HPAD);
        const longlong2* w0 = (const longlong2*)(ws + (hu_l * 4 + 0) * 512);
        const longlong2* w1 = (const longlong2*)(ws + (hu_l * 4 + 1) * 512);
        const longlong2* w2 = (const longlong2*)(ws + (hu_l * 4 + 2) * 512);
        const longlong2* w3 = (const longlong2*)(ws + (hu_l * 4 + 3) * 512);
#pragma unroll 4
        for (int k4 = 0; k4 < 128; k4 += 2) {
            longlong2 hA = hp[k4], hB = hp[k4 + 1];
            longlong2 u0 = w0[k4], u1 = w1[k4], u2 = w2[k4], u3 = w3[k4];
            longlong2 v0 = w0[k4 + 1], v1 = w1[k4 + 1], v2 = w2[k4 + 1], v3 = w3[k4 + 1];
            fma2(a0, (unsigned long long)hA.x, (unsigned long long)u0.x);
            fma2(a1, (unsigned long long)hA.x, (unsigned long long)u1.x);
            fma2(a2, (unsigned long long)hA.x, (unsigned long long)u2.x);
            fma2(a3, (unsigned long long)hA.x, (unsigned long long)u3.x);
            fma2(a0, (unsigned long long)hA.y, (unsigned long long)u0.y);
            fma2(a1, (unsigned long long)hA.y, (unsigned long long)u1.y);
            fma2(a2, (unsigned long long)hA.y, (unsigned long long)u2.y);
            fma2(a3, (unsigned long long)hA.y, (unsigned long long)u3.y);
            fma2(e0, (unsigned long long)hB.x, (unsigned long long)v0.x);
            fma2(e1, (unsigned long long)hB.x, (unsigned long long)v1.x);
            fma2(e2, (unsigned long long)hB.x, (unsigned long long)v2.x);
            fma2(e3, (unsigned long long)hB.x, (unsigned long long)v3.x);
            fma2(e0, (unsigned long long)hB.y, (unsigned long long)v0.y);
            fma2(e1, (unsigned long long)hB.y, (unsigned long long)v1.y);
            fma2(e2, (unsigned long long)hB.y, (unsigned long long)v2.y);
            fma2(e3, (unsigned long long)hB.y, (unsigned long long)v3.y);
        }
        float lo, hi, gi, gf, gg, go, lo2, hi2;
        asm("mov.b64 {%0,%1}, %2;" : "=f"(lo), "=f"(hi) : "l"(a0));
        asm("mov.b64 {%0,%1}, %2;" : "=f"(lo2), "=f"(hi2) : "l"(e0));
        gi = (lo + hi) + (lo2 + hi2) + x0;
        asm("mov.b64 {%0,%1}, %2;" : "=f"(lo), "=f"(hi) : "l"(a1));
        asm("mov.b64 {%0,%1}, %2;" : "=f"(lo2), "=f"(hi2) : "l"(e1));
        gf = (lo + hi) + (lo2 + hi2) + x1;
        asm("mov.b64 {%0,%1}, %2;" : "=f"(lo), "=f"(hi) : "l"(a2));
        asm("mov.b64 {%0,%1}, %2;" : "=f"(lo2), "=f"(hi2) : "l"(e2));
        gg = (lo + hi) + (lo2 + hi2) + x2;
        asm("mov.b64 {%0,%1}, %2;" : "=f"(lo), "=f"(hi) : "l"(a3));
        asm("mov.b64 {%0,%1}, %2;" : "=f"(lo2), "=f"(hi2) : "l"(e3));
        go = (lo + hi) + (lo2 + hi2) + x3;

        float iv = sigf(gi), fv = sigf(gf), gv = tanhfast(gg), ov = sigf(go);
        cc = fv * cc + iv * gv;
        float hv = ov * tanhfast(cc);

        g_hbuf[cur ^ 1][(size_t)b * 512 + hu] = hv;
        if (s >= TSTEPS) {
            int t = s - TSTEPS;
            __nv_bfloat16 hb = __float2bfloat16(hv);
            __nv_bfloat16 lb = __float2bfloat16(hv - __bfloat162float(hb));
            hh2[(size_t)(t * 64 + b) * 1024 + hu]       = hb;
            hh2[(size_t)(t * 64 + b) * 1024 + 512 + hu] = lb;
        }

        grid_sync(ct_b);
        cur ^= 1;
    }
}

// ---------------- launch ----------------
extern "C" void kernel_launch(void* const* d_in, const int* in_sizes, int n_in,
                              void* d_out, int out_size)
{
    const float* feats   = (const float*)d_in[0];
    const int*   labels  = (const int*)  d_in[1];
    const float* W_frame = (const float*)d_in[2];
    const float* b_frame = (const float*)d_in[3];
    const float* embed   = (const float*)d_in[4];
    const float* W_ih    = (const float*)d_in[5];
    const float* W_hh    = (const float*)d_in[6];
    const float* b_ih    = (const float*)d_in[7];
    const float* b_hh    = (const float*)d_in[8];
    const float* W_out   = (const float*)d_in[9];
    const float* b_out   = (const float*)d_in[10];
    float* out = (float*)d_out;

    float* p_xgate;
    __nv_bfloat16 *p_feats2, *p_Wf2, *p_emb2, *p_Wih2e, *p_Wih2d, *p_dece2, *p_hh2, *p_Wo2;
    cudaGetSymbolAddress((void**)&p_xgate,  g_xgate);
    cudaGetSymbolAddress((void**)&p_feats2, g_feats2);
    cudaGetSymbolAddress((void**)&p_Wf2,    g_Wf2);
    cudaGetSymbolAddress((void**)&p_emb2,   g_emb2);
    cudaGetSymbolAddress((void**)&p_Wih2e,  g_Wih2e);
    cudaGetSymbolAddress((void**)&p_Wih2d,  g_Wih2d);
    cudaGetSymbolAddress((void**)&p_dece2,  g_dece2);
    cudaGetSymbolAddress((void**)&p_hh2,    g_hh2);
    cudaGetSymbolAddress((void**)&p_Wo2,    g_Wo2);

    const int smem_lstm = (16384 + 32 * HPAD + 2 * 1152) * sizeof(float);
    cudaFuncSetAttribute(lstm_kernel, cudaFuncAttributeMaxDynamicSharedMemorySize, smem_lstm);
    const int smem_tc = 2 * BUFSZ;
    cudaFuncSetAttribute(mma_tc, cudaFuncAttributeMaxDynamicSharedMemorySize, smem_tc);

    // [0] weight splits + decoder gather
    prep_kernel<<<1184, 256>>>(labels, embed, W_frame, W_ih, W_out,
                               p_Wf2, p_Wih2e, p_Wih2d, p_Wo2, p_dece2);
    // [1] feats split
    fsplit_kernel<<<1184, 256>>>(feats, p_feats2);
    // [2] frame embedding -> g_emb2 (bf16 dual, t-major rows), K=4096
    {
        dim3 grid(MROWS / 128, EDIM / 128);
        mma_tc<<<grid, 256, smem_tc>>>(p_feats2, p_Wf2, b_frame, nullptr,
                                       p_emb2, FDIM, EDIM, 2 * EDIM, 2, 1);
    }
    // [3] encoder x-gates, K=512
    {
        dim3 grid(MROWS / 128, GDIM / 128);
        mma_tc<<<grid, 256, smem_tc>>>(p_emb2, p_Wih2e, b_ih, b_hh,
                                       p_xgate, EDIM, GDIM, GDIM, 0, 0);
    }
    // [4] decoder x-gates, K=512
    {
        dim3 grid(MROWS / 128, GDIM / 128);
        mma_tc<<<grid, 256, smem_tc>>>(p_dece2, p_Wih2d, b_ih, b_hh,
                                       p_xgate + (size_t)MROWS * GDIM, EDIM, GDIM, GDIM, 0, 0);
    }
    // [5] recurrence (profiled launch)
    lstm_kernel<<<RCTAS, 256, smem_lstm>>>(W_hh, p_xgate, p_hh2);
    // [6] logits, K=512
    {
        dim3 grid(MROWS / 128, VPAD / 128);
        mma_tc<<<grid, 256, smem_tc>>>(p_hh2, p_Wo2, b_out, nullptr,
                                       out, HDIM, VDIM, VDIM, 1, 0);
    }
}